// round 10
// baseline (speedup 1.0000x reference)
#include <cuda_runtime.h>
#include <cstddef>

#define S_LEN    256
#define BATCH    256
#define HID      512
#define OUTD     64
#define NSTEP    63
#define KCAT     1088   // 64 (x) + 512 (ctx) + 512 (h)
#define KPAD     1152   // 8 splits * 144
#define KSPLIT   8      // rnn gemm split
#define KSPLIT_Q 16     // q gemm split (klen 32)

typedef unsigned long long ull;

// ---------------- scratch (device globals: allocation-free rule) ----------------
__device__ float g_P[(size_t)S_LEN * BATCH * HID];
__device__ float g_qpart[KSPLIT_Q * BATCH * HID];
__device__ float g_rnnpart[KSPLIT * BATCH * HID];
__device__ float g_rin[BATCH * KPAD];                 // [x | ctx | h | 0-pad]
__device__ float g_WcatT[KPAD * HID];
__device__ float g_bsum[HID];
__device__ float g_h0buf[BATCH * HID];
__device__ float g_h1buf[BATCH * HID];
__device__ float g_x0buf[BATCH * OUTD];
__device__ float g_x1buf[BATCH * OUTD];

__device__ __forceinline__ float fast_tanh(float x) {
    float e = __expf(2.0f * x);
    return 1.0f - __fdividef(2.0f, e + 1.0f);
}

// ---- packed f32x2 helpers ----
__device__ __forceinline__ ull pk2(float lo, float hi) {
    ull r; asm("mov.b64 %0, {%1, %2};" : "=l"(r) : "f"(lo), "f"(hi)); return r;
}
__device__ __forceinline__ ull fma2(ull a, ull b, ull c) {
    ull d; asm("fma.rn.f32x2 %0, %1, %2, %3;" : "=l"(d) : "l"(a), "l"(b), "l"(c)); return d;
}

// ============== P precompute: 128x128 tile, 8x8 microtile, db + FFMA2 ==============
// A staged in smem PRE-DUPLICATED as (a,a) f32x2 pairs: inner loop has zero pk2 movs.
__global__ void __launch_bounds__(256) gemm128(const float* __restrict__ A,
                                               const float* __restrict__ B,
                                               const float* __restrict__ bias,
                                               float* __restrict__ C,
                                               int M, int N, int K) {
    __shared__ __align__(16) ull   As2[2][8][132];   // [buf][k][m] -> pk2(a,a)
    __shared__ __align__(16) float Bs[2][8][128];
    int t  = threadIdx.x;
    int tx = t & 15, ty = t >> 4;
    int m0 = blockIdx.x * 128, n0 = blockIdx.y * 128;

    int ar = t >> 1, ak = (t & 1) * 4;
    int br = t >> 5, bn = (t & 31) * 4;

    const float* Aptr = A + (size_t)(m0 + ar) * K + ak;
    const float* Bptr = B + (size_t)br * N + n0 + bn;

    ull accp[8][4];
#pragma unroll
    for (int jp = 0; jp < 4; jp++) {
        int n = n0 + ((jp < 2) ? tx * 4 + jp * 2 : 64 + tx * 4 + (jp - 2) * 2);
        ull bv = bias ? pk2(bias[n], bias[n + 1]) : 0ull;
#pragma unroll
        for (int i = 0; i < 8; i++) accp[i][jp] = bv;
    }

    float4 a_reg = *(const float4*)(Aptr);
    float4 b_reg = *(const float4*)(Bptr);
    As2[0][ak + 0][ar] = pk2(a_reg.x, a_reg.x);
    As2[0][ak + 1][ar] = pk2(a_reg.y, a_reg.y);
    As2[0][ak + 2][ar] = pk2(a_reg.z, a_reg.z);
    As2[0][ak + 3][ar] = pk2(a_reg.w, a_reg.w);
    *(float4*)(&Bs[0][br][bn]) = b_reg;
    __syncthreads();

    int nc = K / 8, buf = 0;
    for (int c = 0; c < nc; c++) {
        if (c + 1 < nc) {
            a_reg = *(const float4*)(Aptr + (c + 1) * 8);
            b_reg = *(const float4*)(Bptr + (size_t)(c + 1) * 8 * N);
        }
#pragma unroll
        for (int kk = 0; kk < 8; kk++) {
            ulonglong2 a01 = *(const ulonglong2*)(&As2[buf][kk][ty * 4]);
            ulonglong2 a23 = *(const ulonglong2*)(&As2[buf][kk][ty * 4 + 2]);
            ulonglong2 a45 = *(const ulonglong2*)(&As2[buf][kk][64 + ty * 4]);
            ulonglong2 a67 = *(const ulonglong2*)(&As2[buf][kk][64 + ty * 4 + 2]);
            ulonglong2 bq0 = *(const ulonglong2*)(&Bs[buf][kk][tx * 4]);
            ulonglong2 bq1 = *(const ulonglong2*)(&Bs[buf][kk][64 + tx * 4]);
            ull ap[8] = {a01.x, a01.y, a23.x, a23.y, a45.x, a45.y, a67.x, a67.y};
            ull bp[4] = {bq0.x, bq0.y, bq1.x, bq1.y};
#pragma unroll
            for (int i = 0; i < 8; i++)
#pragma unroll
                for (int jp = 0; jp < 4; jp++) accp[i][jp] = fma2(ap[i], bp[jp], accp[i][jp]);
        }
        if (c + 1 < nc) {
            int nb = buf ^ 1;
            As2[nb][ak + 0][ar] = pk2(a_reg.x, a_reg.x);
            As2[nb][ak + 1][ar] = pk2(a_reg.y, a_reg.y);
            As2[nb][ak + 2][ar] = pk2(a_reg.z, a_reg.z);
            As2[nb][ak + 3][ar] = pk2(a_reg.w, a_reg.w);
            *(float4*)(&Bs[nb][br][bn]) = b_reg;
        }
        __syncthreads();
        buf ^= 1;
    }

#pragma unroll
    for (int i = 0; i < 8; i++) {
        int m = m0 + ((i < 4) ? ty * 4 + i : 64 + ty * 4 + (i - 4));
        *(ulonglong2*)(C + (size_t)m * N + n0 + tx * 4)      = make_ulonglong2(accp[i][0], accp[i][1]);
        *(ulonglong2*)(C + (size_t)m * N + n0 + 64 + tx * 4) = make_ulonglong2(accp[i][2], accp[i][3]);
    }
}

// ============== q gemm: single-stage full-K-slice split-K, A-dup smem ==============
template <int KLEN>
__global__ void __launch_bounds__(256) gemmsk(const float* __restrict__ A, int lda,
                                              const float* __restrict__ B,
                                              float* __restrict__ Cpart,
                                              int M, int N) {
    __shared__ __align__(16) ull   As2[KLEN][68];    // [k][m] -> pk2(a,a)
    __shared__ __align__(16) float Bs[KLEN][64];
    int t  = threadIdx.x;
    int tx = t & 15, ty = t >> 4;
    int m0 = blockIdx.x * 64, n0 = blockIdx.y * 64;
    int kb = blockIdx.z * KLEN;

    {
        int row = t >> 2, c0 = t & 3;
        const float* Ar = A + (size_t)(m0 + row) * lda + kb;
#pragma unroll
        for (int i = 0; i < KLEN / 16; i++) {
            int kq = (c0 + i * 4) * 4;
            float4 v = *(const float4*)(Ar + kq);
            As2[kq + 0][row] = pk2(v.x, v.x);
            As2[kq + 1][row] = pk2(v.y, v.y);
            As2[kq + 2][row] = pk2(v.z, v.z);
            As2[kq + 3][row] = pk2(v.w, v.w);
        }
    }
    {
        int kr = t >> 4, nq = (t & 15) * 4;
#pragma unroll
        for (int i = 0; i < KLEN / 16; i++) {
            int k = kr + i * 16;
            *(float4*)(&Bs[k][nq]) = *(const float4*)(B + (size_t)(kb + k) * N + n0 + nq);
        }
    }
    __syncthreads();

    ull acc[4][2] = {};
#pragma unroll 16
    for (int kk = 0; kk < KLEN; kk++) {
        ulonglong2 a01 = *(const ulonglong2*)(&As2[kk][ty * 4]);
        ulonglong2 a23 = *(const ulonglong2*)(&As2[kk][ty * 4 + 2]);
        ulonglong2 b = *(const ulonglong2*)(&Bs[kk][tx * 4]);
        ull ap[4] = {a01.x, a01.y, a23.x, a23.y};
#pragma unroll
        for (int i = 0; i < 4; i++) {
            acc[i][0] = fma2(ap[i], b.x, acc[i][0]);
            acc[i][1] = fma2(ap[i], b.y, acc[i][1]);
        }
    }

    float* Cp = Cpart + (size_t)blockIdx.z * M * N;
#pragma unroll
    for (int i = 0; i < 4; i++)
        *(ulonglong2*)(Cp + (size_t)(m0 + ty * 4 + i) * N + n0 + tx * 4) =
            make_ulonglong2(acc[i][0], acc[i][1]);
}

// ============== rnn gemm: double-buffered 16-chunk split-K, A-dup smem ==============
template <int KLEN>
__global__ void __launch_bounds__(256) gemm64s(const float* __restrict__ A, int lda,
                                               const float* __restrict__ B,
                                               float* __restrict__ Cpart,
                                               int M, int N) {
    __shared__ __align__(16) ull   As2[2][16][68];   // [buf][k][m] -> pk2(a,a)
    __shared__ __align__(16) float Bs[2][16][64];
    constexpr int NC = KLEN / 16;
    int t  = threadIdx.x;
    int tx = t & 15, ty = t >> 4;
    int m0 = blockIdx.x * 64, n0 = blockIdx.y * 64;
    int kbase = blockIdx.z * KLEN;

    ull acc[4][2] = {};

    int arow = t >> 2, akq = (t & 3) * 4;
    int bk = t >> 4, bn = (t & 15) * 4;

    const float* Aptr = A + (size_t)(m0 + arow) * lda + kbase + akq;
    const float* Bptr = B + (size_t)(kbase + bk) * N + n0 + bn;

    float4 av = *(const float4*)(Aptr);
    float4 bv = *(const float4*)(Bptr);
    As2[0][akq + 0][arow] = pk2(av.x, av.x);
    As2[0][akq + 1][arow] = pk2(av.y, av.y);
    As2[0][akq + 2][arow] = pk2(av.z, av.z);
    As2[0][akq + 3][arow] = pk2(av.w, av.w);
    *(float4*)(&Bs[0][bk][bn]) = bv;
    __syncthreads();

    int buf = 0;
#pragma unroll
    for (int c = 0; c < NC; c++) {
        if (c + 1 < NC) {
            av = *(const float4*)(Aptr + (c + 1) * 16);
            bv = *(const float4*)(Bptr + (size_t)(c + 1) * 16 * N);
        }
#pragma unroll
        for (int kk = 0; kk < 16; kk++) {
            ulonglong2 a01 = *(const ulonglong2*)(&As2[buf][kk][ty * 4]);
            ulonglong2 a23 = *(const ulonglong2*)(&As2[buf][kk][ty * 4 + 2]);
            ulonglong2 b = *(const ulonglong2*)(&Bs[buf][kk][tx * 4]);
            ull ap[4] = {a01.x, a01.y, a23.x, a23.y};
#pragma unroll
            for (int i = 0; i < 4; i++) {
                acc[i][0] = fma2(ap[i], b.x, acc[i][0]);
                acc[i][1] = fma2(ap[i], b.y, acc[i][1]);
            }
        }
        if (c + 1 < NC) {
            int nb = buf ^ 1;
            As2[nb][akq + 0][arow] = pk2(av.x, av.x);
            As2[nb][akq + 1][arow] = pk2(av.y, av.y);
            As2[nb][akq + 2][arow] = pk2(av.z, av.z);
            As2[nb][akq + 3][arow] = pk2(av.w, av.w);
            *(float4*)(&Bs[nb][bk][bn]) = bv;
        }
        __syncthreads();
        buf ^= 1;
    }

    float* Cp = Cpart + (size_t)blockIdx.z * M * N;
#pragma unroll
    for (int i = 0; i < 4; i++)
        *(ulonglong2*)(Cp + (size_t)(m0 + ty * 4 + i) * N + n0 + tx * 4) =
            make_ulonglong2(acc[i][0], acc[i][1]);
}

// ---------------- one-time setup ----------------
__global__ void build_wcat(const float* __restrict__ W_ih, const float* __restrict__ W_hh,
                           const float* __restrict__ b_ih, const float* __restrict__ b_hh) {
    int idx = blockIdx.x * 256 + threadIdx.x;
    if (idx < KPAD * HID) {
        int k = idx / HID, h = idx - k * HID;
        float w = 0.0f;
        if (k < 576)       w = W_ih[(size_t)h * 576 + k];
        else if (k < KCAT) w = W_hh[(size_t)h * 512 + (k - 576)];
        g_WcatT[idx] = w;
    }
    if (idx < HID) g_bsum[idx] = b_ih[idx] + b_hh[idx];
}

__global__ void init_state(const float* __restrict__ h0, const float* __restrict__ x0) {
    int i = blockIdx.x * 256 + threadIdx.x;
    if (i < BATCH * HID) g_h0buf[i] = h0[i];
    if (i < BATCH * OUTD) g_x0buf[i] = x0[i];
    if (i < BATCH * (KPAD - KCAT)) {
        int b = i / (KPAD - KCAT), c = i - b * (KPAD - KCAT);
        g_rin[b * KPAD + KCAT + c] = 0.0f;
    }
}

// ============== fused: q-reduce + score + direct softmax + ctx + pack (R8 best) ========
// grid 256 (one block per b), 512 threads (16 warps x 16 s-rows).
__global__ void __launch_bounds__(512, 2) scorectx(const float* __restrict__ v,
                                                   const float* __restrict__ enc,
                                                   const float* __restrict__ xin,
                                                   const float* __restrict__ hin) {
    __shared__ __align__(16) float sq[HID];
    __shared__ __align__(16) float sv[HID];
    __shared__ __align__(16) float ctxp[16][HID];
    __shared__ float wl[16];
    __shared__ float sinvL;

    int b = blockIdx.x, t = threadIdx.x;
    int warp = t >> 5, lane = t & 31;

    {
        float s = 0.0f;
#pragma unroll
        for (int ks = 0; ks < KSPLIT_Q; ks++)
            s += g_qpart[(size_t)ks * BATCH * HID + b * HID + t];
        sq[t] = s;
        sv[t] = v[t];
    }
    __syncthreads();

    const float4* q4 = (const float4*)sq;
    const float4* v4 = (const float4*)sv;

    ull c[8] = {};
    float l = 0.0f;

#pragma unroll 2
    for (int i = 0; i < 16; i++) {
        int s = warp * 16 + i;
        const float4*     Pr = (const float4*)(g_P + ((size_t)s * BATCH + b) * HID);
        const ulonglong2* Er = (const ulonglong2*)(enc + ((size_t)s * BATCH + b) * HID);
        float4 p0 = Pr[lane], p1 = Pr[32 + lane], p2 = Pr[64 + lane], p3 = Pr[96 + lane];
        ulonglong2 E0 = Er[lane], E1 = Er[32 + lane], E2 = Er[64 + lane], E3 = Er[96 + lane];
        float4 q0 = q4[lane], q1 = q4[32 + lane], q2 = q4[64 + lane], q3 = q4[96 + lane];
        float4 v0 = v4[lane], v1 = v4[32 + lane], v2 = v4[64 + lane], v3 = v4[96 + lane];

        float acc = fast_tanh(p0.x + q0.x) * v0.x + fast_tanh(p0.y + q0.y) * v0.y +
                    fast_tanh(p0.z + q0.z) * v0.z + fast_tanh(p0.w + q0.w) * v0.w;
        acc      += fast_tanh(p1.x + q1.x) * v1.x + fast_tanh(p1.y + q1.y) * v1.y +
                    fast_tanh(p1.z + q1.z) * v1.z + fast_tanh(p1.w + q1.w) * v1.w;
        acc      += fast_tanh(p2.x + q2.x) * v2.x + fast_tanh(p2.y + q2.y) * v2.y +
                    fast_tanh(p2.z + q2.z) * v2.z + fast_tanh(p2.w + q2.w) * v2.w;
        acc      += fast_tanh(p3.x + q3.x) * v3.x + fast_tanh(p3.y + q3.y) * v3.y +
                    fast_tanh(p3.z + q3.z) * v3.z + fast_tanh(p3.w + q3.w) * v3.w;
#pragma unroll
        for (int o = 16; o; o >>= 1) acc += __shfl_xor_sync(0xffffffffu, acc, o);

        float w = __expf(acc);      // bounded scores: no max subtraction needed
        l += w;
        ull w2 = pk2(w, w);
        c[0] = fma2(E0.x, w2, c[0]);
        c[1] = fma2(E0.y, w2, c[1]);
        c[2] = fma2(E1.x, w2, c[2]);
        c[3] = fma2(E1.y, w2, c[3]);
        c[4] = fma2(E2.x, w2, c[4]);
        c[5] = fma2(E2.y, w2, c[5]);
        c[6] = fma2(E3.x, w2, c[6]);
        c[7] = fma2(E3.y, w2, c[7]);
    }

    if (lane == 0) wl[warp] = l;
    ulonglong2* cp = (ulonglong2*)ctxp[warp];
    cp[lane]      = make_ulonglong2(c[0], c[1]);
    cp[32 + lane] = make_ulonglong2(c[2], c[3]);
    cp[64 + lane] = make_ulonglong2(c[4], c[5]);
    cp[96 + lane] = make_ulonglong2(c[6], c[7]);
    __syncthreads();

    if (t < 16) {
        float Lp = wl[t];
#pragma unroll
        for (int o = 8; o; o >>= 1) Lp += __shfl_xor_sync(0xffffu, Lp, o);
        if (t == 0) sinvL = __fdividef(1.0f, Lp);
    }
    __syncthreads();

    {
        float cc = 0.0f;
#pragma unroll
        for (int w = 0; w < 16; w++) cc += ctxp[w][t];
        g_rin[b * KPAD + OUTD + t] = cc * sinvL;
        g_rin[b * KPAD + OUTD + HID + t] = hin[b * HID + t];
    }
    if (t < OUTD) g_rin[b * KPAD + t] = xin[b * OUTD + t];
}

// ============== reduce rnn partials + tanh + output head + argmax + one-hot ==============
__global__ void __launch_bounds__(256) outred(const float* __restrict__ Wo,
                                              const float* __restrict__ bo,
                                              float* __restrict__ hout,
                                              float* __restrict__ dout,
                                              float* __restrict__ xnext, int step) {
    int b = blockIdx.x, t = threadIdx.x;
    __shared__ __align__(16) float sh[HID];
    __shared__ float so[OUTD];
    __shared__ int sbest;

    float s0 = g_bsum[t], s1 = g_bsum[t + 256];
#pragma unroll
    for (int ks = 0; ks < KSPLIT; ks++) {
        const float* p = g_rnnpart + (size_t)ks * BATCH * HID + b * HID;
        s0 += p[t];
        s1 += p[t + 256];
    }
    float v0 = fast_tanh(s0), v1 = fast_tanh(s1);
    sh[t] = v0;
    sh[t + 256] = v1;
    hout[b * HID + t] = v0;
    hout[b * HID + t + 256] = v1;
    __syncthreads();

    int warp = t >> 5, lane = t & 31;
    const float4* h4 = (const float4*)sh;
    for (int o = warp; o < OUTD; o += 8) {
        const float4* w4 = (const float4*)(Wo + (size_t)o * HID);
        float acc = 0.0f;
#pragma unroll
        for (int i = 0; i < 4; i++) {
            float4 w = w4[i * 32 + lane], h = h4[i * 32 + lane];
            acc += w.x * h.x + w.y * h.y + w.z * h.z + w.w * h.w;
        }
#pragma unroll
        for (int off = 16; off; off >>= 1) acc += __shfl_xor_sync(0xffffffffu, acc, off);
        if (lane == 0) so[o] = acc + bo[o];
    }
    __syncthreads();
    if (t < OUTD) dout[((size_t)b * OUTD + t) * NSTEP + step] = so[t];
    if (t == 0) {
        float best = so[0];
        int bi = 0;
#pragma unroll
        for (int o = 1; o < OUTD; o++)
            if (so[o] > best) { best = so[o]; bi = o; }
        sbest = bi;
    }
    __syncthreads();
    if (t < OUTD) xnext[b * OUTD + t] = (t == sbest) ? 1.0f : 0.0f;
}

// ---------------- launch ----------------
extern "C" void kernel_launch(void* const* d_in, const int* in_sizes, int n_in,
                              void* d_out, int out_size) {
    const float* sos = (const float*)d_in[0];
    const float* h0  = (const float*)d_in[1];
    const float* enc = (const float*)d_in[2];
    const float* Wa  = (const float*)d_in[3];
    const float* ba  = (const float*)d_in[4];
    const float* v   = (const float*)d_in[5];
    const float* Wih = (const float*)d_in[6];
    const float* bih = (const float*)d_in[7];
    const float* Whh = (const float*)d_in[8];
    const float* bhh = (const float*)d_in[9];
    const float* Wo  = (const float*)d_in[10];
    const float* bo  = (const float*)d_in[11];
    float* out = (float*)d_out;

    float *pP, *pqp, *prp, *pr, *pW, *ph[2], *px[2];
    cudaGetSymbolAddress((void**)&pP,  g_P);
    cudaGetSymbolAddress((void**)&pqp, g_qpart);
    cudaGetSymbolAddress((void**)&prp, g_rnnpart);
    cudaGetSymbolAddress((void**)&pr,  g_rin);
    cudaGetSymbolAddress((void**)&pW,  g_WcatT);
    cudaGetSymbolAddress((void**)&ph[0], g_h0buf);
    cudaGetSymbolAddress((void**)&ph[1], g_h1buf);
    cudaGetSymbolAddress((void**)&px[0], g_x0buf);
    cudaGetSymbolAddress((void**)&px[1], g_x1buf);

    init_state<<<512, 256>>>(h0, sos);
    build_wcat<<<(KPAD * HID + 255) / 256, 256>>>(Wih, Whh, bih, bhh);
    // R8 grid order (m-tiles on x) — R9's swap is reverted pending attribution
    gemm128<<<dim3(S_LEN * BATCH / 128, HID / 128), 256>>>(enc, Wa + 512 * HID, ba, pP,
                                                           S_LEN * BATCH, HID, HID);

    for (int t = 0; t < NSTEP; t++) {
        int cur = t & 1, nxt = cur ^ 1;
        // q partials = h_t @ Wa[:512], split-K 16x32
        gemmsk<32><<<dim3(BATCH / 64, HID / 64, KSPLIT_Q), 256>>>(ph[cur], HID, Wa, pqp,
                                                                  BATCH, HID);
        scorectx<<<BATCH, 512>>>(v, enc, px[cur], ph[cur]);
        // rnn partials = rnn_in @ WcatT, split-K 8x144, double-buffered
        gemm64s<144><<<dim3(BATCH / 64, HID / 64, KSPLIT), 256>>>(pr, KPAD, pW, prp,
                                                                  BATCH, HID);
        outred<<<BATCH, 256>>>(Wo, bo, ph[nxt], out, px[nxt], t);
    }
}

// round 11
// speedup vs baseline: 1.1228x; 1.1228x over previous
#include <cuda_runtime.h>
#include <cstddef>

#define S_LEN    256
#define BATCH    256
#define HID      512
#define OUTD     64
#define NSTEP    63
#define KCAT     1088   // 64 (x) + 512 (ctx) + 512 (h)
#define KPAD     1152   // 8 splits * 144
#define KSPLIT   8      // rnn gemm split
#define KSPLIT_Q 16     // q gemm split (klen 32)

typedef unsigned long long ull;

// ---------------- scratch (device globals: allocation-free rule) ----------------
__device__ float g_P[(size_t)S_LEN * BATCH * HID];
__device__ float g_qpart[KSPLIT_Q * BATCH * HID];
__device__ float g_rnnpart[KSPLIT * BATCH * HID];
__device__ float g_rin[BATCH * KPAD];                 // [x | ctx | h | 0-pad]
__device__ float g_WcatT[KPAD * HID];
__device__ float g_bsum[HID];
__device__ float g_h0buf[BATCH * HID];
__device__ float g_h1buf[BATCH * HID];
__device__ float g_x0buf[BATCH * OUTD];
__device__ float g_x1buf[BATCH * OUTD];

__device__ __forceinline__ float fast_tanh(float x) {
    float e = __expf(2.0f * x);
    return 1.0f - __fdividef(2.0f, e + 1.0f);
}

// ---- packed f32x2 helpers ----
__device__ __forceinline__ ull pk2(float lo, float hi) {
    ull r; asm("mov.b64 %0, {%1, %2};" : "=l"(r) : "f"(lo), "f"(hi)); return r;
}
__device__ __forceinline__ ull fma2(ull a, ull b, ull c) {
    ull d; asm("fma.rn.f32x2 %0, %1, %2, %3;" : "=l"(d) : "l"(a), "l"(b), "l"(c)); return d;
}

// ============== P precompute: 128x128 tile, 8x8 microtile, db + FFMA2 (R8 exact) ========
__global__ void __launch_bounds__(256) gemm128(const float* __restrict__ A,
                                               const float* __restrict__ B,
                                               const float* __restrict__ bias,
                                               float* __restrict__ C,
                                               int M, int N, int K) {
    __shared__ __align__(16) float As[2][8][132];
    __shared__ __align__(16) float Bs[2][8][128];
    int t  = threadIdx.x;
    int tx = t & 15, ty = t >> 4;
    int m0 = blockIdx.x * 128, n0 = blockIdx.y * 128;

    int ar = t >> 1, ak = (t & 1) * 4;
    int br = t >> 5, bn = (t & 31) * 4;

    const float* Aptr = A + (size_t)(m0 + ar) * K + ak;
    const float* Bptr = B + (size_t)br * N + n0 + bn;

    ull accp[8][4];
#pragma unroll
    for (int jp = 0; jp < 4; jp++) {
        int n = n0 + ((jp < 2) ? tx * 4 + jp * 2 : 64 + tx * 4 + (jp - 2) * 2);
        ull bv = bias ? pk2(bias[n], bias[n + 1]) : 0ull;
#pragma unroll
        for (int i = 0; i < 8; i++) accp[i][jp] = bv;
    }

    float4 a_reg = *(const float4*)(Aptr);
    float4 b_reg = *(const float4*)(Bptr);
    As[0][ak + 0][ar] = a_reg.x;
    As[0][ak + 1][ar] = a_reg.y;
    As[0][ak + 2][ar] = a_reg.z;
    As[0][ak + 3][ar] = a_reg.w;
    *(float4*)(&Bs[0][br][bn]) = b_reg;
    __syncthreads();

    int nc = K / 8, buf = 0;
    for (int c = 0; c < nc; c++) {
        if (c + 1 < nc) {
            a_reg = *(const float4*)(Aptr + (c + 1) * 8);
            b_reg = *(const float4*)(Bptr + (size_t)(c + 1) * 8 * N);
        }
#pragma unroll
        for (int kk = 0; kk < 8; kk++) {
            float4 a0 = *(const float4*)(&As[buf][kk][ty * 4]);
            float4 a1 = *(const float4*)(&As[buf][kk][64 + ty * 4]);
            ulonglong2 bq0 = *(const ulonglong2*)(&Bs[buf][kk][tx * 4]);
            ulonglong2 bq1 = *(const ulonglong2*)(&Bs[buf][kk][64 + tx * 4]);
            float av[8] = {a0.x, a0.y, a0.z, a0.w, a1.x, a1.y, a1.z, a1.w};
            ull bp[4] = {bq0.x, bq0.y, bq1.x, bq1.y};
#pragma unroll
            for (int i = 0; i < 8; i++) {
                ull ap = pk2(av[i], av[i]);
#pragma unroll
                for (int jp = 0; jp < 4; jp++) accp[i][jp] = fma2(ap, bp[jp], accp[i][jp]);
            }
        }
        if (c + 1 < nc) {
            int nb = buf ^ 1;
            As[nb][ak + 0][ar] = a_reg.x;
            As[nb][ak + 1][ar] = a_reg.y;
            As[nb][ak + 2][ar] = a_reg.z;
            As[nb][ak + 3][ar] = a_reg.w;
            *(float4*)(&Bs[nb][br][bn]) = b_reg;
        }
        __syncthreads();
        buf ^= 1;
    }

#pragma unroll
    for (int i = 0; i < 8; i++) {
        int m = m0 + ((i < 4) ? ty * 4 + i : 64 + ty * 4 + (i - 4));
        *(ulonglong2*)(C + (size_t)m * N + n0 + tx * 4)      = make_ulonglong2(accp[i][0], accp[i][1]);
        *(ulonglong2*)(C + (size_t)m * N + n0 + 64 + tx * 4) = make_ulonglong2(accp[i][2], accp[i][3]);
    }
}

// ============== q gemm: single-stage full-K-slice split-K (R8 exact) ==============
template <int KLEN>
__global__ void __launch_bounds__(256) gemmsk(const float* __restrict__ A, int lda,
                                              const float* __restrict__ B,
                                              float* __restrict__ Cpart,
                                              int M, int N) {
    __shared__ __align__(16) float As[KLEN][68];
    __shared__ __align__(16) float Bs[KLEN][64];
    int t  = threadIdx.x;
    int tx = t & 15, ty = t >> 4;
    int m0 = blockIdx.x * 64, n0 = blockIdx.y * 64;
    int kb = blockIdx.z * KLEN;

    {
        int row = t >> 2, c0 = t & 3;
        const float* Ar = A + (size_t)(m0 + row) * lda + kb;
#pragma unroll
        for (int i = 0; i < KLEN / 16; i++) {
            int kq = (c0 + i * 4) * 4;
            float4 v = *(const float4*)(Ar + kq);
            As[kq + 0][row] = v.x;
            As[kq + 1][row] = v.y;
            As[kq + 2][row] = v.z;
            As[kq + 3][row] = v.w;
        }
    }
    {
        int kr = t >> 4, nq = (t & 15) * 4;
#pragma unroll
        for (int i = 0; i < KLEN / 16; i++) {
            int k = kr + i * 16;
            *(float4*)(&Bs[k][nq]) = *(const float4*)(B + (size_t)(kb + k) * N + n0 + nq);
        }
    }
    __syncthreads();

    ull acc[4][2] = {};
#pragma unroll 16
    for (int kk = 0; kk < KLEN; kk++) {
        float4 a = *(const float4*)(&As[kk][ty * 4]);
        ulonglong2 b = *(const ulonglong2*)(&Bs[kk][tx * 4]);
        float av[4] = {a.x, a.y, a.z, a.w};
#pragma unroll
        for (int i = 0; i < 4; i++) {
            ull ap = pk2(av[i], av[i]);
            acc[i][0] = fma2(ap, b.x, acc[i][0]);
            acc[i][1] = fma2(ap, b.y, acc[i][1]);
        }
    }

    float* Cp = Cpart + (size_t)blockIdx.z * M * N;
#pragma unroll
    for (int i = 0; i < 4; i++)
        *(ulonglong2*)(Cp + (size_t)(m0 + ty * 4 + i) * N + n0 + tx * 4) =
            make_ulonglong2(acc[i][0], acc[i][1]);
}

// ============== rnn gemm: double-buffered 16-chunk split-K + FFMA2 (R8 exact) ==========
template <int KLEN>
__global__ void __launch_bounds__(256) gemm64s(const float* __restrict__ A, int lda,
                                               const float* __restrict__ B,
                                               float* __restrict__ Cpart,
                                               int M, int N) {
    __shared__ __align__(16) float As[2][16][68];
    __shared__ __align__(16) float Bs[2][16][64];
    constexpr int NC = KLEN / 16;
    int t  = threadIdx.x;
    int tx = t & 15, ty = t >> 4;
    int m0 = blockIdx.x * 64, n0 = blockIdx.y * 64;
    int kbase = blockIdx.z * KLEN;

    ull acc[4][2] = {};

    int arow = t >> 2, akq = (t & 3) * 4;
    int bk = t >> 4, bn = (t & 15) * 4;

    const float* Aptr = A + (size_t)(m0 + arow) * lda + kbase + akq;
    const float* Bptr = B + (size_t)(kbase + bk) * N + n0 + bn;

    float4 av = *(const float4*)(Aptr);
    float4 bv = *(const float4*)(Bptr);
    As[0][akq + 0][arow] = av.x;
    As[0][akq + 1][arow] = av.y;
    As[0][akq + 2][arow] = av.z;
    As[0][akq + 3][arow] = av.w;
    *(float4*)(&Bs[0][bk][bn]) = bv;
    __syncthreads();

    int buf = 0;
#pragma unroll
    for (int c = 0; c < NC; c++) {
        if (c + 1 < NC) {
            av = *(const float4*)(Aptr + (c + 1) * 16);
            bv = *(const float4*)(Bptr + (size_t)(c + 1) * 16 * N);
        }
#pragma unroll
        for (int kk = 0; kk < 16; kk++) {
            float4 a = *(const float4*)(&As[buf][kk][ty * 4]);
            ulonglong2 b = *(const ulonglong2*)(&Bs[buf][kk][tx * 4]);
            float aa[4] = {a.x, a.y, a.z, a.w};
#pragma unroll
            for (int i = 0; i < 4; i++) {
                ull ap = pk2(aa[i], aa[i]);
                acc[i][0] = fma2(ap, b.x, acc[i][0]);
                acc[i][1] = fma2(ap, b.y, acc[i][1]);
            }
        }
        if (c + 1 < NC) {
            int nb = buf ^ 1;
            As[nb][akq + 0][arow] = av.x;
            As[nb][akq + 1][arow] = av.y;
            As[nb][akq + 2][arow] = av.z;
            As[nb][akq + 3][arow] = av.w;
            *(float4*)(&Bs[nb][bk][bn]) = bv;
        }
        __syncthreads();
        buf ^= 1;
    }

    float* Cp = Cpart + (size_t)blockIdx.z * M * N;
#pragma unroll
    for (int i = 0; i < 4; i++)
        *(ulonglong2*)(Cp + (size_t)(m0 + ty * 4 + i) * N + n0 + tx * 4) =
            make_ulonglong2(acc[i][0], acc[i][1]);
}

// ---------------- one-time setup ----------------
__global__ void build_wcat(const float* __restrict__ W_ih, const float* __restrict__ W_hh,
                           const float* __restrict__ b_ih, const float* __restrict__ b_hh) {
    int idx = blockIdx.x * 256 + threadIdx.x;
    if (idx < KPAD * HID) {
        int k = idx / HID, h = idx - k * HID;
        float w = 0.0f;
        if (k < 576)       w = W_ih[(size_t)h * 576 + k];
        else if (k < KCAT) w = W_hh[(size_t)h * 512 + (k - 576)];
        g_WcatT[idx] = w;
    }
    if (idx < HID) g_bsum[idx] = b_ih[idx] + b_hh[idx];
}

__global__ void init_state(const float* __restrict__ h0, const float* __restrict__ x0) {
    int i = blockIdx.x * 256 + threadIdx.x;
    if (i < BATCH * HID) g_h0buf[i] = h0[i];
    if (i < BATCH * OUTD) g_x0buf[i] = x0[i];
    if (i < BATCH * (KPAD - KCAT)) {
        int b = i / (KPAD - KCAT), c = i - b * (KPAD - KCAT);
        g_rin[b * KPAD + KCAT + c] = 0.0f;
    }
}

// ============== fused 2-PHASE: q-reduce + scores -> smem, then streaming ctx ==========
// Phase 1 streams P (scores, MUFU-heavy); phase 2 streams enc (pure fma, no serial
// chain, no shfl). Same 268 MB total; the per-iter reduce->exp->accumulate dependency
// of the fused version is gone. grid 256 (block per b), 512 threads.
__global__ void __launch_bounds__(512, 2) scorectx(const float* __restrict__ v,
                                                   const float* __restrict__ enc,
                                                   const float* __restrict__ xin,
                                                   const float* __restrict__ hin) {
    __shared__ __align__(16) float sq[HID];
    __shared__ __align__(16) float sv[HID];
    __shared__ __align__(16) float sa[S_LEN];      // exp(score)
    __shared__ __align__(16) float ctxs[4][HID];   // per-s-group ctx partials
    __shared__ float red[8];
    __shared__ float sinvL;

    int b = blockIdx.x, t = threadIdx.x;
    int warp = t >> 5, lane = t & 31;

    // q = deterministic sum of split-K partials
    {
        float s = 0.0f;
#pragma unroll
        for (int ks = 0; ks < KSPLIT_Q; ks++)
            s += g_qpart[(size_t)ks * BATCH * HID + b * HID + t];
        sq[t] = s;
        sv[t] = v[t];
    }
    __syncthreads();

    const float4* q4 = (const float4*)sq;
    const float4* v4 = (const float4*)sv;

    // ---- phase 1: scores (warp w owns s = w*16 .. w*16+15) ----
#pragma unroll 2
    for (int i = 0; i < 16; i++) {
        int s = warp * 16 + i;
        const float4* Pr = (const float4*)(g_P + ((size_t)s * BATCH + b) * HID);
        float4 p0 = Pr[lane], p1 = Pr[32 + lane], p2 = Pr[64 + lane], p3 = Pr[96 + lane];
        float4 q0 = q4[lane], q1 = q4[32 + lane], q2 = q4[64 + lane], q3 = q4[96 + lane];
        float4 v0 = v4[lane], v1 = v4[32 + lane], v2 = v4[64 + lane], v3 = v4[96 + lane];

        float acc = fast_tanh(p0.x + q0.x) * v0.x + fast_tanh(p0.y + q0.y) * v0.y +
                    fast_tanh(p0.z + q0.z) * v0.z + fast_tanh(p0.w + q0.w) * v0.w;
        acc      += fast_tanh(p1.x + q1.x) * v1.x + fast_tanh(p1.y + q1.y) * v1.y +
                    fast_tanh(p1.z + q1.z) * v1.z + fast_tanh(p1.w + q1.w) * v1.w;
        acc      += fast_tanh(p2.x + q2.x) * v2.x + fast_tanh(p2.y + q2.y) * v2.y +
                    fast_tanh(p2.z + q2.z) * v2.z + fast_tanh(p2.w + q2.w) * v2.w;
        acc      += fast_tanh(p3.x + q3.x) * v3.x + fast_tanh(p3.y + q3.y) * v3.y +
                    fast_tanh(p3.z + q3.z) * v3.z + fast_tanh(p3.w + q3.w) * v3.w;
#pragma unroll
        for (int o = 16; o; o >>= 1) acc += __shfl_xor_sync(0xffffffffu, acc, o);
        if (lane == 0) sa[s] = __expf(acc);   // bounded scores: direct softmax
    }
    __syncthreads();

    // ---- sum of exp -> 1/L ----
    if (t < S_LEN) {
        float sm = sa[t];
#pragma unroll
        for (int o = 16; o; o >>= 1) sm += __shfl_xor_sync(0xffffffffu, sm, o);
        if (lane == 0) red[warp] = sm;
    }
    __syncthreads();
    if (t < 8) {
        float r = red[t];
#pragma unroll
        for (int o = 4; o; o >>= 1) r += __shfl_xor_sync(0xffu, r, o);
        if (t == 0) sinvL = __fdividef(1.0f, r);
    }
    __syncthreads();

    // ---- phase 2: ctx — 4 s-groups x 128 threads, each thread a float4 of h ----
    {
        int sg = t >> 7;                 // 0..3
        int h4 = (t & 127) << 2;         // h offset
        float4 c = make_float4(0.f, 0.f, 0.f, 0.f);
        const float* base = enc + (size_t)b * HID + h4;
#pragma unroll 4
        for (int so = 0; so < S_LEN; so += 4) {
            int s = so + sg;
            float a = sa[s];
            float4 e4 = *(const float4*)(base + (size_t)s * BATCH * HID);
            c.x = fmaf(a, e4.x, c.x);
            c.y = fmaf(a, e4.y, c.y);
            c.z = fmaf(a, e4.z, c.z);
            c.w = fmaf(a, e4.w, c.w);
        }
        *(float4*)(&ctxs[sg][h4]) = c;
    }
    __syncthreads();

    // ---- combine groups, normalize, pack rnn_in = [x | ctx | h] ----
    {
        float cc = ctxs[0][t] + ctxs[1][t] + ctxs[2][t] + ctxs[3][t];
        g_rin[b * KPAD + OUTD + t] = cc * sinvL;
        g_rin[b * KPAD + OUTD + HID + t] = hin[b * HID + t];
    }
    if (t < OUTD) g_rin[b * KPAD + t] = xin[b * OUTD + t];
}

// ============== reduce rnn partials + tanh + output head + argmax + one-hot ==============
__global__ void __launch_bounds__(256) outred(const float* __restrict__ Wo,
                                              const float* __restrict__ bo,
                                              float* __restrict__ hout,
                                              float* __restrict__ dout,
                                              float* __restrict__ xnext, int step) {
    int b = blockIdx.x, t = threadIdx.x;
    __shared__ __align__(16) float sh[HID];
    __shared__ float so[OUTD];
    __shared__ int sbest;

    float s0 = g_bsum[t], s1 = g_bsum[t + 256];
#pragma unroll
    for (int ks = 0; ks < KSPLIT; ks++) {
        const float* p = g_rnnpart + (size_t)ks * BATCH * HID + b * HID;
        s0 += p[t];
        s1 += p[t + 256];
    }
    float v0 = fast_tanh(s0), v1 = fast_tanh(s1);
    sh[t] = v0;
    sh[t + 256] = v1;
    hout[b * HID + t] = v0;
    hout[b * HID + t + 256] = v1;
    __syncthreads();

    int warp = t >> 5, lane = t & 31;
    const float4* h4 = (const float4*)sh;
    for (int o = warp; o < OUTD; o += 8) {
        const float4* w4 = (const float4*)(Wo + (size_t)o * HID);
        float acc = 0.0f;
#pragma unroll
        for (int i = 0; i < 4; i++) {
            float4 w = w4[i * 32 + lane], h = h4[i * 32 + lane];
            acc += w.x * h.x + w.y * h.y + w.z * h.z + w.w * h.w;
        }
#pragma unroll
        for (int off = 16; off; off >>= 1) acc += __shfl_xor_sync(0xffffffffu, acc, off);
        if (lane == 0) so[o] = acc + bo[o];
    }
    __syncthreads();
    if (t < OUTD) dout[((size_t)b * OUTD + t) * NSTEP + step] = so[t];
    if (t == 0) {
        float best = so[0];
        int bi = 0;
#pragma unroll
        for (int o = 1; o < OUTD; o++)
            if (so[o] > best) { best = so[o]; bi = o; }
        sbest = bi;
    }
    __syncthreads();
    if (t < OUTD) xnext[b * OUTD + t] = (t == sbest) ? 1.0f : 0.0f;
}

// ---------------- launch ----------------
extern "C" void kernel_launch(void* const* d_in, const int* in_sizes, int n_in,
                              void* d_out, int out_size) {
    const float* sos = (const float*)d_in[0];
    const float* h0  = (const float*)d_in[1];
    const float* enc = (const float*)d_in[2];
    const float* Wa  = (const float*)d_in[3];
    const float* ba  = (const float*)d_in[4];
    const float* v   = (const float*)d_in[5];
    const float* Wih = (const float*)d_in[6];
    const float* bih = (const float*)d_in[7];
    const float* Whh = (const float*)d_in[8];
    const float* bhh = (const float*)d_in[9];
    const float* Wo  = (const float*)d_in[10];
    const float* bo  = (const float*)d_in[11];
    float* out = (float*)d_out;

    float *pP, *pqp, *prp, *pr, *pW, *ph[2], *px[2];
    cudaGetSymbolAddress((void**)&pP,  g_P);
    cudaGetSymbolAddress((void**)&pqp, g_qpart);
    cudaGetSymbolAddress((void**)&prp, g_rnnpart);
    cudaGetSymbolAddress((void**)&pr,  g_rin);
    cudaGetSymbolAddress((void**)&pW,  g_WcatT);
    cudaGetSymbolAddress((void**)&ph[0], g_h0buf);
    cudaGetSymbolAddress((void**)&ph[1], g_h1buf);
    cudaGetSymbolAddress((void**)&px[0], g_x0buf);
    cudaGetSymbolAddress((void**)&px[1], g_x1buf);

    init_state<<<512, 256>>>(h0, sos);
    build_wcat<<<(KPAD * HID + 255) / 256, 256>>>(Wih, Whh, bih, bhh);
    gemm128<<<dim3(S_LEN * BATCH / 128, HID / 128), 256>>>(enc, Wa + 512 * HID, ba, pP,
                                                           S_LEN * BATCH, HID, HID);

    for (int t = 0; t < NSTEP; t++) {
        int cur = t & 1, nxt = cur ^ 1;
        // q partials = h_t @ Wa[:512], split-K 16x32
        gemmsk<32><<<dim3(BATCH / 64, HID / 64, KSPLIT_Q), 256>>>(ph[cur], HID, Wa, pqp,
                                                                  BATCH, HID);
        scorectx<<<BATCH, 512>>>(v, enc, px[cur], ph[cur]);
        // rnn partials = rnn_in @ WcatT, split-K 8x144, double-buffered
        gemm64s<144><<<dim3(BATCH / 64, HID / 64, KSPLIT), 256>>>(pr, KPAD, pW, prp,
                                                                  BATCH, HID);
        outred<<<BATCH, 256>>>(Wo, bo, ph[nxt], out, px[nxt], t);
    }
}

// round 14
// speedup vs baseline: 1.1485x; 1.0229x over previous
#include <cuda_runtime.h>
#include <cstddef>

#define S_LEN    256
#define BATCH    256
#define HID      512
#define OUTD     64
#define NSTEP    63
#define KCAT     1088   // 64 (x) + 512 (ctx) + 512 (h)
#define KPAD     1152   // 8 splits * 144
#define KSPLIT   8      // rnn gemm split
#define KSPLIT_Q 16     // q gemm split (klen 32)

typedef unsigned long long ull;

// ---------------- scratch (device globals: allocation-free rule) ----------------
__device__ float g_P[(size_t)S_LEN * BATCH * HID];
__device__ float g_qpart[KSPLIT_Q * BATCH * HID];
__device__ float g_rnnpart[KSPLIT * BATCH * HID];
__device__ float g_rin[BATCH * KPAD];                 // [x | ctx | h | 0-pad]
__device__ float g_WcatT[KPAD * HID];
__device__ float g_bsum[HID];
__device__ float g_h0buf[BATCH * HID];
__device__ float g_h1buf[BATCH * HID];
__device__ float g_x0buf[BATCH * OUTD];
__device__ float g_x1buf[BATCH * OUTD];

__device__ __forceinline__ float fast_tanh(float x) {
    float e = __expf(2.0f * x);
    return 1.0f - __fdividef(2.0f, e + 1.0f);
}

// ---- packed f32x2 helpers ----
__device__ __forceinline__ ull pk2(float lo, float hi) {
    ull r; asm("mov.b64 %0, {%1, %2};" : "=l"(r) : "f"(lo), "f"(hi)); return r;
}
__device__ __forceinline__ ull fma2(ull a, ull b, ull c) {
    ull d; asm("fma.rn.f32x2 %0, %1, %2, %3;" : "=l"(d) : "l"(a), "l"(b), "l"(c)); return d;
}

// ============== P precompute: 128x128 tile, 8x8 microtile, db + FFMA2 ==============
// (a) __launch_bounds__(256,2) to guarantee 2 CTA/SM,
// (b) n-fast grid (x = n-tiles) so CTAs sharing an A m-tile are co-scheduled -> A
// comes from DRAM once, L2 3x, instead of DRAM 4x.
__global__ void __launch_bounds__(256, 2) gemm128(const float* __restrict__ A,
                                                  const float* __restrict__ B,
                                                  const float* __restrict__ bias,
                                                  float* __restrict__ C,
                                                  int M, int N, int K) {
    __shared__ __align__(16) float As[2][8][132];
    __shared__ __align__(16) float Bs[2][8][128];
    int t  = threadIdx.x;
    int tx = t & 15, ty = t >> 4;
    int m0 = blockIdx.y * 128, n0 = blockIdx.x * 128;

    int ar = t >> 1, ak = (t & 1) * 4;
    int br = t >> 5, bn = (t & 31) * 4;

    const float* Aptr = A + (size_t)(m0 + ar) * K + ak;
    const float* Bptr = B + (size_t)br * N + n0 + bn;

    ull accp[8][4];
#pragma unroll
    for (int jp = 0; jp < 4; jp++) {
        int n = n0 + ((jp < 2) ? tx * 4 + jp * 2 : 64 + tx * 4 + (jp - 2) * 2);
        ull bv = bias ? pk2(bias[n], bias[n + 1]) : 0ull;
#pragma unroll
        for (int i = 0; i < 8; i++) accp[i][jp] = bv;
    }

    float4 a_reg = *(const float4*)(Aptr);
    float4 b_reg = *(const float4*)(Bptr);
    As[0][ak + 0][ar] = a_reg.x;
    As[0][ak + 1][ar] = a_reg.y;
    As[0][ak + 2][ar] = a_reg.z;
    As[0][ak + 3][ar] = a_reg.w;
    *(float4*)(&Bs[0][br][bn]) = b_reg;
    __syncthreads();

    int nc = K / 8, buf = 0;
    for (int c = 0; c < nc; c++) {
        if (c + 1 < nc) {
            a_reg = *(const float4*)(Aptr + (c + 1) * 8);
            b_reg = *(const float4*)(Bptr + (size_t)(c + 1) * 8 * N);
        }
#pragma unroll
        for (int kk = 0; kk < 8; kk++) {
            float4 a0 = *(const float4*)(&As[buf][kk][ty * 4]);
            float4 a1 = *(const float4*)(&As[buf][kk][64 + ty * 4]);
            ulonglong2 bq0 = *(const ulonglong2*)(&Bs[buf][kk][tx * 4]);
            ulonglong2 bq1 = *(const ulonglong2*)(&Bs[buf][kk][64 + tx * 4]);
            float av[8] = {a0.x, a0.y, a0.z, a0.w, a1.x, a1.y, a1.z, a1.w};
            ull bp[4] = {bq0.x, bq0.y, bq1.x, bq1.y};
#pragma unroll
            for (int i = 0; i < 8; i++) {
                ull ap = pk2(av[i], av[i]);
#pragma unroll
                for (int jp = 0; jp < 4; jp++) accp[i][jp] = fma2(ap, bp[jp], accp[i][jp]);
            }
        }
        if (c + 1 < nc) {
            int nb = buf ^ 1;
            As[nb][ak + 0][ar] = a_reg.x;
            As[nb][ak + 1][ar] = a_reg.y;
            As[nb][ak + 2][ar] = a_reg.z;
            As[nb][ak + 3][ar] = a_reg.w;
            *(float4*)(&Bs[nb][br][bn]) = b_reg;
        }
        __syncthreads();
        buf ^= 1;
    }

#pragma unroll
    for (int i = 0; i < 8; i++) {
        int m = m0 + ((i < 4) ? ty * 4 + i : 64 + ty * 4 + (i - 4));
        *(ulonglong2*)(C + (size_t)m * N + n0 + tx * 4)      = make_ulonglong2(accp[i][0], accp[i][1]);
        *(ulonglong2*)(C + (size_t)m * N + n0 + 64 + tx * 4) = make_ulonglong2(accp[i][2], accp[i][3]);
    }
}

// ============== q gemm: single-stage full-K-slice split-K (R8/R11 exact) ==============
template <int KLEN>
__global__ void __launch_bounds__(256) gemmsk(const float* __restrict__ A, int lda,
                                              const float* __restrict__ B,
                                              float* __restrict__ Cpart,
                                              int M, int N) {
    __shared__ __align__(16) float As[KLEN][68];
    __shared__ __align__(16) float Bs[KLEN][64];
    int t  = threadIdx.x;
    int tx = t & 15, ty = t >> 4;
    int m0 = blockIdx.x * 64, n0 = blockIdx.y * 64;
    int kb = blockIdx.z * KLEN;

    {
        int row = t >> 2, c0 = t & 3;
        const float* Ar = A + (size_t)(m0 + row) * lda + kb;
#pragma unroll
        for (int i = 0; i < KLEN / 16; i++) {
            int kq = (c0 + i * 4) * 4;
            float4 v = *(const float4*)(Ar + kq);
            As[kq + 0][row] = v.x;
            As[kq + 1][row] = v.y;
            As[kq + 2][row] = v.z;
            As[kq + 3][row] = v.w;
        }
    }
    {
        int kr = t >> 4, nq = (t & 15) * 4;
#pragma unroll
        for (int i = 0; i < KLEN / 16; i++) {
            int k = kr + i * 16;
            *(float4*)(&Bs[k][nq]) = *(const float4*)(B + (size_t)(kb + k) * N + n0 + nq);
        }
    }
    __syncthreads();

    ull acc[4][2] = {};
#pragma unroll 16
    for (int kk = 0; kk < KLEN; kk++) {
        float4 a = *(const float4*)(&As[kk][ty * 4]);
        ulonglong2 b = *(const ulonglong2*)(&Bs[kk][tx * 4]);
        float av[4] = {a.x, a.y, a.z, a.w};
#pragma unroll
        for (int i = 0; i < 4; i++) {
            ull ap = pk2(av[i], av[i]);
            acc[i][0] = fma2(ap, b.x, acc[i][0]);
            acc[i][1] = fma2(ap, b.y, acc[i][1]);
        }
    }

    float* Cp = Cpart + (size_t)blockIdx.z * M * N;
#pragma unroll
    for (int i = 0; i < 4; i++)
        *(ulonglong2*)(Cp + (size_t)(m0 + ty * 4 + i) * N + n0 + tx * 4) =
            make_ulonglong2(acc[i][0], acc[i][1]);
}

// ============== rnn gemm: double-buffered 16-chunk split-K + FFMA2 (R8/R11 exact) ======
template <int KLEN>
__global__ void __launch_bounds__(256) gemm64s(const float* __restrict__ A, int lda,
                                               const float* __restrict__ B,
                                               float* __restrict__ Cpart,
                                               int M, int N) {
    __shared__ __align__(16) float As[2][16][68];
    __shared__ __align__(16) float Bs[2][16][64];
    constexpr int NC = KLEN / 16;
    int t  = threadIdx.x;
    int tx = t & 15, ty = t >> 4;
    int m0 = blockIdx.x * 64, n0 = blockIdx.y * 64;
    int kbase = blockIdx.z * KLEN;

    ull acc[4][2] = {};

    int arow = t >> 2, akq = (t & 3) * 4;
    int bk = t >> 4, bn = (t & 15) * 4;

    const float* Aptr = A + (size_t)(m0 + arow) * lda + kbase + akq;
    const float* Bptr = B + (size_t)(kbase + bk) * N + n0 + bn;

    float4 av = *(const float4*)(Aptr);
    float4 bv = *(const float4*)(Bptr);
    As[0][akq + 0][arow] = av.x;
    As[0][akq + 1][arow] = av.y;
    As[0][akq + 2][arow] = av.z;
    As[0][akq + 3][arow] = av.w;
    *(float4*)(&Bs[0][bk][bn]) = bv;
    __syncthreads();

    int buf = 0;
#pragma unroll
    for (int c = 0; c < NC; c++) {
        if (c + 1 < NC) {
            av = *(const float4*)(Aptr + (c + 1) * 16);
            bv = *(const float4*)(Bptr + (size_t)(c + 1) * 16 * N);
        }
#pragma unroll
        for (int kk = 0; kk < 16; kk++) {
            float4 a = *(const float4*)(&As[buf][kk][ty * 4]);
            ulonglong2 b = *(const ulonglong2*)(&Bs[buf][kk][tx * 4]);
            float aa[4] = {a.x, a.y, a.z, a.w};
#pragma unroll
            for (int i = 0; i < 4; i++) {
                ull ap = pk2(aa[i], aa[i]);
                acc[i][0] = fma2(ap, b.x, acc[i][0]);
                acc[i][1] = fma2(ap, b.y, acc[i][1]);
            }
        }
        if (c + 1 < NC) {
            int nb = buf ^ 1;
            As[nb][akq + 0][arow] = av.x;
            As[nb][akq + 1][arow] = av.y;
            As[nb][akq + 2][arow] = av.z;
            As[nb][akq + 3][arow] = av.w;
            *(float4*)(&Bs[nb][bk][bn]) = bv;
        }
        __syncthreads();
        buf ^= 1;
    }

    float* Cp = Cpart + (size_t)blockIdx.z * M * N;
#pragma unroll
    for (int i = 0; i < 4; i++)
        *(ulonglong2*)(Cp + (size_t)(m0 + ty * 4 + i) * N + n0 + tx * 4) =
            make_ulonglong2(acc[i][0], acc[i][1]);
}

// ---------------- one-time setup ----------------
__global__ void build_wcat(const float* __restrict__ W_ih, const float* __restrict__ W_hh,
                           const float* __restrict__ b_ih, const float* __restrict__ b_hh) {
    int idx = blockIdx.x * 256 + threadIdx.x;
    if (idx < KPAD * HID) {
        int k = idx / HID, h = idx - k * HID;
        float w = 0.0f;
        if (k < 576)       w = W_ih[(size_t)h * 576 + k];
        else if (k < KCAT) w = W_hh[(size_t)h * 512 + (k - 576)];
        g_WcatT[idx] = w;
    }
    if (idx < HID) g_bsum[idx] = b_ih[idx] + b_hh[idx];
}

__global__ void init_state(const float* __restrict__ h0, const float* __restrict__ x0) {
    int i = blockIdx.x * 256 + threadIdx.x;
    if (i < BATCH * HID) g_h0buf[i] = h0[i];
    if (i < BATCH * OUTD) g_x0buf[i] = x0[i];
    if (i < BATCH * (KPAD - KCAT)) {
        int b = i / (KPAD - KCAT), c = i - b * (KPAD - KCAT);
        g_rin[b * KPAD + KCAT + c] = 0.0f;
    }
}

// ============== fused 2-PHASE scorectx (R11 exact) ==============
__global__ void __launch_bounds__(512, 2) scorectx(const float* __restrict__ v,
                                                   const float* __restrict__ enc,
                                                   const float* __restrict__ xin,
                                                   const float* __restrict__ hin) {
    __shared__ __align__(16) float sq[HID];
    __shared__ __align__(16) float sv[HID];
    __shared__ __align__(16) float sa[S_LEN];      // exp(score)
    __shared__ __align__(16) float ctxs[4][HID];   // per-s-group ctx partials
    __shared__ float red[8];
    __shared__ float sinvL;

    int b = blockIdx.x, t = threadIdx.x;
    int warp = t >> 5, lane = t & 31;

    {
        float s = 0.0f;
#pragma unroll
        for (int ks = 0; ks < KSPLIT_Q; ks++)
            s += g_qpart[(size_t)ks * BATCH * HID + b * HID + t];
        sq[t] = s;
        sv[t] = v[t];
    }
    __syncthreads();

    const float4* q4 = (const float4*)sq;
    const float4* v4 = (const float4*)sv;

    // ---- phase 1: scores ----
#pragma unroll 2
    for (int i = 0; i < 16; i++) {
        int s = warp * 16 + i;
        const float4* Pr = (const float4*)(g_P + ((size_t)s * BATCH + b) * HID);
        float4 p0 = Pr[lane], p1 = Pr[32 + lane], p2 = Pr[64 + lane], p3 = Pr[96 + lane];
        float4 q0 = q4[lane], q1 = q4[32 + lane], q2 = q4[64 + lane], q3 = q4[96 + lane];
        float4 v0 = v4[lane], v1 = v4[32 + lane], v2 = v4[64 + lane], v3 = v4[96 + lane];

        float acc = fast_tanh(p0.x + q0.x) * v0.x + fast_tanh(p0.y + q0.y) * v0.y +
                    fast_tanh(p0.z + q0.z) * v0.z + fast_tanh(p0.w + q0.w) * v0.w;
        acc      += fast_tanh(p1.x + q1.x) * v1.x + fast_tanh(p1.y + q1.y) * v1.y +
                    fast_tanh(p1.z + q1.z) * v1.z + fast_tanh(p1.w + q1.w) * v1.w;
        acc      += fast_tanh(p2.x + q2.x) * v2.x + fast_tanh(p2.y + q2.y) * v2.y +
                    fast_tanh(p2.z + q2.z) * v2.z + fast_tanh(p2.w + q2.w) * v2.w;
        acc      += fast_tanh(p3.x + q3.x) * v3.x + fast_tanh(p3.y + q3.y) * v3.y +
                    fast_tanh(p3.z + q3.z) * v3.z + fast_tanh(p3.w + q3.w) * v3.w;
#pragma unroll
        for (int o = 16; o; o >>= 1) acc += __shfl_xor_sync(0xffffffffu, acc, o);
        if (lane == 0) sa[s] = __expf(acc);   // bounded scores: direct softmax
    }
    __syncthreads();

    // ---- sum of exp -> 1/L ----
    if (t < S_LEN) {
        float sm = sa[t];
#pragma unroll
        for (int o = 16; o; o >>= 1) sm += __shfl_xor_sync(0xffffffffu, sm, o);
        if (lane == 0) red[warp] = sm;
    }
    __syncthreads();
    if (t < 8) {
        float r = red[t];
#pragma unroll
        for (int o = 4; o; o >>= 1) r += __shfl_xor_sync(0xffu, r, o);
        if (t == 0) sinvL = __fdividef(1.0f, r);
    }
    __syncthreads();

    // ---- phase 2: ctx — 4 s-groups x 128 threads ----
    {
        int sg = t >> 7;
        int h4 = (t & 127) << 2;
        float4 c = make_float4(0.f, 0.f, 0.f, 0.f);
        const float* base = enc + (size_t)b * HID + h4;
#pragma unroll 4
        for (int so = 0; so < S_LEN; so += 4) {
            int s = so + sg;
            float a = sa[s];
            float4 e4 = *(const float4*)(base + (size_t)s * BATCH * HID);
            c.x = fmaf(a, e4.x, c.x);
            c.y = fmaf(a, e4.y, c.y);
            c.z = fmaf(a, e4.z, c.z);
            c.w = fmaf(a, e4.w, c.w);
        }
        *(float4*)(&ctxs[sg][h4]) = c;
    }
    __syncthreads();

    // ---- combine groups, normalize, pack rnn_in = [x | ctx | h] ----
    {
        float cc = ctxs[0][t] + ctxs[1][t] + ctxs[2][t] + ctxs[3][t];
        g_rin[b * KPAD + OUTD + t] = cc * sinvL;
        g_rin[b * KPAD + OUTD + HID + t] = hin[b * HID + t];
    }
    if (t < OUTD) g_rin[b * KPAD + t] = xin[b * OUTD + t];
}

// ============== reduce rnn partials + tanh + output head + argmax + one-hot ==============
__global__ void __launch_bounds__(256) outred(const float* __restrict__ Wo,
                                              const float* __restrict__ bo,
                                              float* __restrict__ hout,
                                              float* __restrict__ dout,
                                              float* __restrict__ xnext, int step) {
    int b = blockIdx.x, t = threadIdx.x;
    __shared__ __align__(16) float sh[HID];
    __shared__ float so[OUTD];
    __shared__ int sbest;

    float s0 = g_bsum[t], s1 = g_bsum[t + 256];
#pragma unroll
    for (int ks = 0; ks < KSPLIT; ks++) {
        const float* p = g_rnnpart + (size_t)ks * BATCH * HID + b * HID;
        s0 += p[t];
        s1 += p[t + 256];
    }
    float v0 = fast_tanh(s0), v1 = fast_tanh(s1);
    sh[t] = v0;
    sh[t + 256] = v1;
    hout[b * HID + t] = v0;
    hout[b * HID + t + 256] = v1;
    __syncthreads();

    int warp = t >> 5, lane = t & 31;
    const float4* h4 = (const float4*)sh;
    for (int o = warp; o < OUTD; o += 8) {
        const float4* w4 = (const float4*)(Wo + (size_t)o * HID);
        float acc = 0.0f;
#pragma unroll
        for (int i = 0; i < 4; i++) {
            float4 w = w4[i * 32 + lane], h = h4[i * 32 + lane];
            acc += w.x * h.x + w.y * h.y + w.z * h.z + w.w * h.w;
        }
#pragma unroll
        for (int off = 16; off; off >>= 1) acc += __shfl_xor_sync(0xffffffffu, acc, off);
        if (lane == 0) so[o] = acc + bo[o];
    }
    __syncthreads();
    if (t < OUTD) dout[((size_t)b * OUTD + t) * NSTEP + step] = so[t];
    if (t == 0) {
        float best = so[0];
        int bi = 0;
#pragma unroll
        for (int o = 1; o < OUTD; o++)
            if (so[o] > best) { best = so[o]; bi = o; }
        sbest = bi;
    }
    __syncthreads();
    if (t < OUTD) xnext[b * OUTD + t] = (t == sbest) ? 1.0f : 0.0f;
}

// ---------------- launch ----------------
extern "C" void kernel_launch(void* const* d_in, const int* in_sizes, int n_in,
                              void* d_out, int out_size) {
    const float* sos = (const float*)d_in[0];
    const float* h0  = (const float*)d_in[1];
    const float* enc = (const float*)d_in[2];
    const float* Wa  = (const float*)d_in[3];
    const float* ba  = (const float*)d_in[4];
    const float* v   = (const float*)d_in[5];
    const float* Wih = (const float*)d_in[6];
    const float* bih = (const float*)d_in[7];
    const float* Whh = (const float*)d_in[8];
    const float* bhh = (const float*)d_in[9];
    const float* Wo  = (const float*)d_in[10];
    const float* bo  = (const float*)d_in[11];
    float* out = (float*)d_out;

    float *pP, *pqp, *prp, *pr, *pW, *ph[2], *px[2];
    cudaGetSymbolAddress((void**)&pP,  g_P);
    cudaGetSymbolAddress((void**)&pqp, g_qpart);
    cudaGetSymbolAddress((void**)&prp, g_rnnpart);
    cudaGetSymbolAddress((void**)&pr,  g_rin);
    cudaGetSymbolAddress((void**)&pW,  g_WcatT);
    cudaGetSymbolAddress((void**)&ph[0], g_h0buf);
    cudaGetSymbolAddress((void**)&ph[1], g_h1buf);
    cudaGetSymbolAddress((void**)&px[0], g_x0buf);
    cudaGetSymbolAddress((void**)&px[1], g_x1buf);

    init_state<<<512, 256>>>(h0, sos);
    build_wcat<<<(KPAD * HID + 255) / 256, 256>>>(Wih, Whh, bih, bhh);
    // n-fast grid: x = n-tiles (4), y = m-tiles (512) -> A m-tile shared by 4 adjacent CTAs
    gemm128<<<dim3(HID / 128, S_LEN * BATCH / 128), 256>>>(enc, Wa + 512 * HID, ba, pP,
                                                           S_LEN * BATCH, HID, HID);

    for (int t = 0; t < NSTEP; t++) {
        int cur = t & 1, nxt = cur ^ 1;
        // q partials = h_t @ Wa[:512], split-K 16x32
        gemmsk<32><<<dim3(BATCH / 64, HID / 64, KSPLIT_Q), 256>>>(ph[cur], HID, Wa, pqp,
                                                                  BATCH, HID);
        scorectx<<<BATCH, 512>>>(v, enc, px[cur], ph[cur]);
        // rnn partials = rnn_in @ WcatT, split-K 8x144, double-buffered
        gemm64s<144><<<dim3(BATCH / 64, HID / 64, KSPLIT), 256>>>(pr, KPAD, pW, prp,
                                                                  BATCH, HID);
        outred<<<BATCH, 256>>>(Wo, bo, ph[nxt], out, px[nxt], t);
    }
}